// round 12
// baseline (speedup 1.0000x reference)
#include <cuda_runtime.h>
#include <cstdint>

// Problem dims (fixed)
#define B_  16
#define U_  64
#define T_  128
#define E_  128
#define HID_ 256
#define H_  4
#define ENC_H_ 128
#define IN_DIM_ 32

typedef unsigned long long ull;

// Scratch (device globals: no allocation allowed)
__device__ float g_qu[B_ * U_ * HID_];    // ue @ fw1[:E]          (1024 x 256)
__device__ float g_kh[B_ * T_ * HID_];    // te @ fw1[E:]          (2048 x 256)
__device__ float g_qb[H_ * HID_];         // head_q @ fw1[:E] + fb1 (4 x 256)
__device__ float g_part[4][B_ * H_ * U_ * T_];  // d-quadrant partial sums

// Packed weights: Wp[k2][c] = (W[2k2][c], W[2k2+1][c]) as float2
#define UW0_OFF 0
#define UW1_OFF 4096
#define UW2_OFF 20480
#define TW0_OFF 36864
#define TW1_OFF 40960
#define TW2_OFF 57344
#define FW1_OFF 73728
#define WPACK_TOTAL 139264
__device__ float g_wpack[WPACK_TOTAL];

// ---- packed f32x2 helpers (Blackwell) ----
__device__ __forceinline__ ull add2(ull a, ull b) {
    ull r;
    asm("add.rn.f32x2 %0, %1, %2;" : "=l"(r) : "l"(a), "l"(b));
    return r;
}
__device__ __forceinline__ void fma2(ull& acc, ull a, ull b) {
    asm("fma.rn.f32x2 %0, %1, %2, %0;" : "+l"(acc) : "l"(a), "l"(b));
}
__device__ __forceinline__ ull relu2(ull x) {
    float lo, hi;
    asm("mov.b64 {%0,%1}, %2;" : "=f"(lo), "=f"(hi) : "l"(x));
    lo = fmaxf(lo, 0.f);
    hi = fmaxf(hi, 0.f);
    ull r;
    asm("mov.b64 %0, {%1,%2};" : "=l"(r) : "f"(lo), "f"(hi));
    return r;
}
__device__ __forceinline__ float hsum2(ull x) {
    float lo, hi;
    asm("mov.b64 {%0,%1}, %2;" : "=f"(lo), "=f"(hi) : "l"(x));
    return lo + hi;
}

// ---------------------------------------------------------------------------
// Pack kernel: interleave k-pairs of every weight matrix (proven in R11).
// ---------------------------------------------------------------------------
__global__ __launch_bounds__(256) void pack_kernel(
    const float* __restrict__ uw0, const float* __restrict__ uw1,
    const float* __restrict__ uw2, const float* __restrict__ tw0,
    const float* __restrict__ tw1, const float* __restrict__ tw2,
    const float* __restrict__ fw1)
{
    const int b = blockIdx.x;
    const int t = threadIdx.x;
    const float* src;
    int C, dstoff, pair0;
    if      (b < 8)   { src = uw0; C = 128; dstoff = UW0_OFF; pair0 = b * 256; }
    else if (b < 40)  { src = uw1; C = 128; dstoff = UW1_OFF; pair0 = (b - 8) * 256; }
    else if (b < 72)  { src = uw2; C = 128; dstoff = UW2_OFF; pair0 = (b - 40) * 256; }
    else if (b < 80)  { src = tw0; C = 128; dstoff = TW0_OFF; pair0 = (b - 72) * 256; }
    else if (b < 112) { src = tw1; C = 128; dstoff = TW1_OFF; pair0 = (b - 80) * 256; }
    else if (b < 144) { src = tw2; C = 128; dstoff = TW2_OFF; pair0 = (b - 112) * 256; }
    else              { src = fw1; C = 256; dstoff = FW1_OFF; pair0 = (b - 144) * 256; }

    int p = pair0 + t;
    int k2 = (C == 128) ? (p >> 7) : (p >> 8);
    int c  = (C == 128) ? (p & 127) : (p & 255);
    float lo = src[(2 * k2) * C + c];
    float hi = src[(2 * k2 + 1) * C + c];
    *(float2*)&g_wpack[dstoff + p * 2] = make_float2(lo, hi);
}

// ---------------------------------------------------------------------------
// enc3: weights-broadcast encoder.
// Block = 32 rows, 512 threads = 16 warps. lane = row (0..31), warp wid owns
// cols c0 = wid*8 .. c0+7.  Activations stored pair-transposed in smem:
// buf[k2][row] (float2) with row-stride of PADR pairs.
// Weight loads are warp-uniform __ldg from the packed layout (broadcast).
// Blocks [0,32) = UAV, [32,96) = task, 96 = qb.
// ---------------------------------------------------------------------------
#define PADR 33   // row capacity per k2 slice (in float2 units)

// generic layer: in bufIn (K2 pairs), out 8 col values for (lane) row
__device__ __forceinline__ void layer8(
    ull acc[4], const float* bufIn, int K2,
    const float* __restrict__ wp, int C, int c0, int lane)
{
    acc[0] = acc[1] = acc[2] = acc[3] = 0ULL;
    ull a4[4];  // accumulate pairs across 4 col-pairs: acc[i] covers cols c0+2i, c0+2i+1
    (void)a4;
    #pragma unroll 4
    for (int k2 = 0; k2 < K2; ++k2) {
        ull a = *(const ull*)(bufIn + (size_t)(k2 * PADR + lane) * 2);
        ulonglong2 w01 = __ldg((const ulonglong2*)(wp + (size_t)(k2 * C + c0) * 2));
        ulonglong2 w23 = __ldg((const ulonglong2*)(wp + (size_t)(k2 * C + c0 + 4) * 2));
        fma2(acc[0], a, w01.x);
        fma2(acc[1], a, w01.y);
        fma2(acc[2], a, w23.x);
        fma2(acc[3], a, w23.y);
    }
}

// acc layout: acc[j] is f32x2 where lo/hi are (even-k, odd-k) partial sums of
// TWO DIFFERENT columns? No — w01.x packs (W[2k2][c0], W[2k2+1][c0]) and `a`
// packs (act[2k2], act[2k2+1]) so acc[0] = pairwise partials of col c0 only.
// We need 8 cols -> 8 accumulators. Fixed version below.
__device__ __forceinline__ void layer8_full(
    ull acc[8], const float* bufIn, int K2,
    const float* __restrict__ wp, int C, int c0, int lane)
{
    #pragma unroll
    for (int j = 0; j < 8; ++j) acc[j] = 0ULL;
    #pragma unroll 4
    for (int k2 = 0; k2 < K2; ++k2) {
        ull a = *(const ull*)(bufIn + (size_t)(k2 * PADR + lane) * 2);
        ulonglong2 wA = __ldg((const ulonglong2*)(wp + (size_t)(k2 * C + c0) * 2));
        ulonglong2 wB = __ldg((const ulonglong2*)(wp + (size_t)(k2 * C + c0 + 2) * 2));
        ulonglong2 wC = __ldg((const ulonglong2*)(wp + (size_t)(k2 * C + c0 + 4) * 2));
        ulonglong2 wD = __ldg((const ulonglong2*)(wp + (size_t)(k2 * C + c0 + 6) * 2));
        fma2(acc[0], a, wA.x); fma2(acc[1], a, wA.y);
        fma2(acc[2], a, wB.x); fma2(acc[3], a, wB.y);
        fma2(acc[4], a, wC.x); fma2(acc[5], a, wC.y);
        fma2(acc[6], a, wD.x); fma2(acc[7], a, wD.y);
    }
}

__global__ __launch_bounds__(512) void enc3_kernel(
    const float* __restrict__ uav_feat, const float* __restrict__ task_feat,
    const float* __restrict__ ub0, const float* __restrict__ ub1,
    const float* __restrict__ ub2, const float* __restrict__ tb0,
    const float* __restrict__ tb1, const float* __restrict__ tb2,
    const float* __restrict__ head_q, const float* __restrict__ fw1,
    const float* __restrict__ fb1)
{
    const int bx = blockIdx.x;
    const int tid = threadIdx.x;

    // ---------------- qb block ----------------
    if (bx == 96) {
        if (tid < HID_) {
            int d = tid;
            #pragma unroll
            for (int h = 0; h < H_; ++h) {
                float acc = fb1[d];
                #pragma unroll 8
                for (int k = 0; k < E_; ++k)
                    acc += head_q[h * E_ + k] * fw1[k * HID_ + d];
                g_qb[h * HID_ + d] = acc;
            }
        }
        return;
    }

    const int is_task = (bx >= 32);
    const float* x   = is_task ? task_feat : uav_feat;
    const float* wp0 = g_wpack + (is_task ? TW0_OFF : UW0_OFF);
    const float* wp1 = g_wpack + (is_task ? TW1_OFF : UW1_OFF);
    const float* wp2 = g_wpack + (is_task ? TW2_OFF : UW2_OFF);
    const float* wpf = g_wpack + FW1_OFF + (is_task ? (size_t)E_ * HID_ : 0);
    const float* b0  = is_task ? tb0 : ub0;
    const float* b1  = is_task ? tb1 : ub1;
    const float* b2  = is_task ? tb2 : ub2;
    float* gout      = is_task ? g_kh : g_qu;
    const int row0   = (is_task ? (bx - 32) : bx) * 32;

    // smem: pair-transposed activation buffers
    __shared__ float xsP[16 * PADR * 2];      // K2=16, 32 rows
    __shared__ float bufA[64 * PADR * 2];     // K2=64
    __shared__ float bufB[64 * PADR * 2];

    // fill xsP: 512 threads, 512 float2 elements: k2 = tid&15, row = tid>>4
    {
        int k2  = tid & 15;
        int row = tid >> 4;
        float2 v = *(const float2*)&x[(size_t)(row0 + row) * IN_DIM_ + 2 * k2];
        *(float2*)&xsP[(size_t)(k2 * PADR + row) * 2] = v;
    }
    __syncthreads();

    const int lane = tid & 31;     // row
    const int wid  = tid >> 5;     // 0..15 -> col group
    const int c0   = wid * 8;

    ull acc[8];
    float outv[8];

    // ---- layer 0: K=32 (K2=16), C=128, relu ----
    layer8_full(acc, xsP, 16, wp0, ENC_H_, c0, lane);
    #pragma unroll
    for (int j = 0; j < 8; ++j)
        outv[j] = fmaxf(hsum2(acc[j]) + b0[c0 + j], 0.f);
    __syncthreads();   // xsP no longer needed; bufA writes after all reads
    #pragma unroll
    for (int j = 0; j < 4; ++j)
        *(float2*)&bufA[(size_t)(((c0 >> 1) + j) * PADR + lane) * 2] =
            make_float2(outv[2 * j], outv[2 * j + 1]);
    __syncthreads();

    // ---- layer 1: K=128 (K2=64), C=128, relu ----
    layer8_full(acc, bufA, 64, wp1, ENC_H_, c0, lane);
    #pragma unroll
    for (int j = 0; j < 8; ++j)
        outv[j] = fmaxf(hsum2(acc[j]) + b1[c0 + j], 0.f);
    __syncthreads();
    #pragma unroll
    for (int j = 0; j < 4; ++j)
        *(float2*)&bufB[(size_t)(((c0 >> 1) + j) * PADR + lane) * 2] =
            make_float2(outv[2 * j], outv[2 * j + 1]);
    __syncthreads();

    // ---- layer 2: K=128 (K2=64), C=128, no relu -> bufA ----
    layer8_full(acc, bufB, 64, wp2, ENC_H_, c0, lane);
    #pragma unroll
    for (int j = 0; j < 8; ++j)
        outv[j] = hsum2(acc[j]) + b2[c0 + j];
    __syncthreads();
    #pragma unroll
    for (int j = 0; j < 4; ++j)
        *(float2*)&bufA[(size_t)(((c0 >> 1) + j) * PADR + lane) * 2] =
            make_float2(outv[2 * j], outv[2 * j + 1]);
    __syncthreads();

    // ---- projection: K=128 (K2=64), C=256, two col passes ----
    #pragma unroll
    for (int p = 0; p < 2; ++p) {
        int pc = c0 + 128 * p;
        layer8_full(acc, bufA, 64, wpf, HID_, pc, lane);
        float* o = gout + (size_t)(row0 + lane) * HID_ + pc;
        float4 v0 = make_float4(hsum2(acc[0]), hsum2(acc[1]),
                                hsum2(acc[2]), hsum2(acc[3]));
        float4 v1 = make_float4(hsum2(acc[4]), hsum2(acc[5]),
                                hsum2(acc[6]), hsum2(acc[7]));
        *(float4*)o = v0;
        *(float4*)(o + 4) = v1;
    }
}

// ---------------------------------------------------------------------------
// Stage E (d-split): partial[dq][z][u][t] =
//   sum_{d in quad} relu(qu[b,u,d]+qb[h,d]+kh[b,t,d]) * fw2[d]
// Block: (dq, z). Tile 64u x 128t x 64d, 512 threads, thread tile 4u x 4t.
// ---------------------------------------------------------------------------
#define DQ 64
#define QSTRIDE 68
#define SMEM_E_FLOATS (64 * QSTRIDE + 128 * QSTRIDE + DQ)
#define SMEM_E_BYTES  (SMEM_E_FLOATS * 4)

__global__ __launch_bounds__(512, 2) void stageE_k(
    const float* __restrict__ fw2)
{
    extern __shared__ float smem[];
    float* qs   = smem;                        // [64][68]
    float* ks   = smem + 64 * QSTRIDE;         // [128][68]
    float* fw2s = ks + 128 * QSTRIDE;          // [64]

    const int tid = threadIdx.x;
    const int dq  = blockIdx.x;               // 0..3
    const int z   = blockIdx.y;               // b*H + h
    const int b   = z >> 2;
    const int h   = z & 3;
    const int d0  = dq * DQ;

    if (tid < DQ / 4)
        ((float4*)fw2s)[tid] = ((const float4*)(fw2 + d0))[tid];

    {
        const float4* qb4 = (const float4*)(g_qb + h * HID_ + d0);
        #pragma unroll
        for (int p = 0; p < 2; ++p) {
            int idx = tid + p * 512;
            int u   = idx >> 4;
            int d4  = idx & 15;
            float4 a = ((const float4*)(g_qu + (size_t)(b * U_ + u) * HID_ + d0))[d4];
            float4 qb = qb4[d4];
            a.x += qb.x; a.y += qb.y; a.z += qb.z; a.w += qb.w;
            ((float4*)(qs + u * QSTRIDE))[d4] = a;
        }
    }
    {
        #pragma unroll
        for (int p = 0; p < 4; ++p) {
            int idx = tid + p * 512;
            int t   = idx >> 4;
            int d4  = idx & 15;
            ((float4*)(ks + t * QSTRIDE))[d4] =
                ((const float4*)(g_kh + (size_t)(b * T_ + t) * HID_ + d0))[d4];
        }
    }
    __syncthreads();

    const int tg = tid & 31;       // t = tg + 32*jj
    const int ug = tid >> 5;       // u = 4*ug + i

    ull acc[4][4];
    #pragma unroll
    for (int i = 0; i < 4; ++i)
        #pragma unroll
        for (int jj = 0; jj < 4; ++jj) acc[i][jj] = 0ULL;

    const float* qbase = qs + (ug * 4) * QSTRIDE;
    const float* kbase = ks + tg * QSTRIDE;

    #pragma unroll 4
    for (int d4 = 0; d4 < DQ / 4; ++d4) {
        ulonglong2 wv = *(const ulonglong2*)(fw2s + d4 * 4);
        ulonglong2 qv[4], kv[4];
        #pragma unroll
        for (int i = 0; i < 4; ++i)
            qv[i] = *(const ulonglong2*)(qbase + i * QSTRIDE + d4 * 4);
        #pragma unroll
        for (int jj = 0; jj < 4; ++jj)
            kv[jj] = *(const ulonglong2*)(kbase + jj * 32 * QSTRIDE + d4 * 4);

        #pragma unroll
        for (int i = 0; i < 4; ++i) {
            #pragma unroll
            for (int jj = 0; jj < 4; ++jj) {
                fma2(acc[i][jj], relu2(add2(qv[i].x, kv[jj].x)), wv.x);
                fma2(acc[i][jj], relu2(add2(qv[i].y, kv[jj].y)), wv.y);
            }
        }
    }

    float* part = g_part[dq] + (size_t)z * U_ * T_;
    #pragma unroll
    for (int i = 0; i < 4; ++i) {
        float* row = part + (ug * 4 + i) * T_ + tg;
        #pragma unroll
        for (int jj = 0; jj < 4; ++jj)
            row[jj * 32] = hsum2(acc[i][jj]);
    }
}

// ---------------------------------------------------------------------------
// Combine: out = sum of 4 d-quadrant partials + fb2 (2 float4 per thread)
// ---------------------------------------------------------------------------
__global__ __launch_bounds__(256) void combine_kernel(
    float* __restrict__ out, const float* __restrict__ fb2)
{
    const float bias = fb2[0];
    int i0 = blockIdx.x * 512 + threadIdx.x;
    #pragma unroll
    for (int p = 0; p < 2; ++p) {
        int i = i0 + p * 256;
        float4 a = ((const float4*)g_part[0])[i];
        float4 b = ((const float4*)g_part[1])[i];
        float4 c = ((const float4*)g_part[2])[i];
        float4 d = ((const float4*)g_part[3])[i];
        float4 r;
        r.x = a.x + b.x + c.x + d.x + bias;
        r.y = a.y + b.y + c.y + d.y + bias;
        r.z = a.z + b.z + c.z + d.z + bias;
        r.w = a.w + b.w + c.w + d.w + bias;
        ((float4*)out)[i] = r;
    }
}

// ---------------------------------------------------------------------------
extern "C" void kernel_launch(void* const* d_in, const int* in_sizes, int n_in,
                              void* d_out, int out_size)
{
    const float* uav_feat = (const float*)d_in[0];
    const float* task_feat = (const float*)d_in[1];
    const float* uw0 = (const float*)d_in[2];
    const float* ub0 = (const float*)d_in[3];
    const float* uw1 = (const float*)d_in[4];
    const float* ub1 = (const float*)d_in[5];
    const float* uw2 = (const float*)d_in[6];
    const float* ub2 = (const float*)d_in[7];
    const float* tw0 = (const float*)d_in[8];
    const float* tb0 = (const float*)d_in[9];
    const float* tw1 = (const float*)d_in[10];
    const float* tb1 = (const float*)d_in[11];
    const float* tw2 = (const float*)d_in[12];
    const float* tb2 = (const float*)d_in[13];
    const float* head_q = (const float*)d_in[14];
    const float* fw1 = (const float*)d_in[15];
    const float* fb1 = (const float*)d_in[16];
    const float* fw2 = (const float*)d_in[17];
    const float* fb2 = (const float*)d_in[18];
    float* out = (float*)d_out;

    cudaFuncSetAttribute(stageE_k,
                         cudaFuncAttributeMaxDynamicSharedMemorySize,
                         SMEM_E_BYTES);

    // 1) pack weights into k-pair-interleaved layout
    pack_kernel<<<272, 256>>>(uw0, uw1, uw2, tw0, tw1, tw2, fw1);

    // 2) encoders + qb (97 blocks x 512 threads, 32 rows/block, broadcast W)
    enc3_kernel<<<97, 512>>>(uav_feat, task_feat,
                             ub0, ub1, ub2, tb0, tb1, tb2,
                             head_q, fw1, fb1);

    // 3) Stage E over 4 d-quadrants x 64 (b,h)
    dim3 grid(4, B_ * H_);
    stageE_k<<<grid, 512, SMEM_E_BYTES>>>(fw2);

    // 4) combine partials + bias
    combine_kernel<<<256, 256>>>(out, fb2);
}

// round 14
// speedup vs baseline: 2.1687x; 2.1687x over previous
#include <cuda_runtime.h>
#include <cstdint>

// Problem dims (fixed)
#define B_  16
#define U_  64
#define T_  128
#define E_  128
#define HID_ 256
#define H_  4
#define ENC_H_ 128
#define IN_DIM_ 32

typedef unsigned long long ull;

// Scratch (device globals: no allocation allowed)
__device__ float g_qu[B_ * U_ * HID_];    // ue @ fw1[:E]          (1024 x 256)
__device__ float g_kh[B_ * T_ * HID_];    // te @ fw1[E:]          (2048 x 256)
__device__ float g_qb[H_ * HID_];         // head_q @ fw1[:E] + fb1 (4 x 256)
__device__ float g_part[2][B_ * H_ * U_ * T_];  // d-half partial sums

// ---- packed f32x2 helpers (Blackwell) ----
__device__ __forceinline__ ull add2(ull a, ull b) {
    ull r;
    asm("add.rn.f32x2 %0, %1, %2;" : "=l"(r) : "l"(a), "l"(b));
    return r;
}
__device__ __forceinline__ void fma2(ull& acc, ull a, ull b) {
    asm("fma.rn.f32x2 %0, %1, %2, %0;" : "+l"(acc) : "l"(a), "l"(b));
}
__device__ __forceinline__ ull relu2(ull x) {
    float lo, hi;
    asm("mov.b64 {%0,%1}, %2;" : "=f"(lo), "=f"(hi) : "l"(x));
    lo = fmaxf(lo, 0.f);
    hi = fmaxf(hi, 0.f);
    ull r;
    asm("mov.b64 %0, {%1,%2};" : "=l"(r) : "f"(lo), "f"(hi));
    return r;
}
__device__ __forceinline__ float hsum2(ull x) {
    float lo, hi;
    asm("mov.b64 {%0,%1}, %2;" : "=f"(lo), "=f"(hi) : "l"(x));
    return lo + hi;
}

// ---------------------------------------------------------------------------
// Encoder k8 step: 4 rows x 1 col x 8 k.  8 scalar weight LDGs front-batched
// (MLP 8, coalesced across j), acts broadcast LDS.128 (2 f4 per row).
// ---------------------------------------------------------------------------
__device__ __forceinline__ void enc_step8(
    float acc[4], const float* __restrict__ wcol, int C,
    const float* a0, const float* a1, const float* a2, const float* a3)
{
    float w0 = __ldg(wcol);
    float w1 = __ldg(wcol + C);
    float w2 = __ldg(wcol + 2 * C);
    float w3 = __ldg(wcol + 3 * C);
    float w4 = __ldg(wcol + 4 * C);
    float w5 = __ldg(wcol + 5 * C);
    float w6 = __ldg(wcol + 6 * C);
    float w7 = __ldg(wcol + 7 * C);
    float4 x0a = *(const float4*)a0, x0b = *(const float4*)(a0 + 4);
    float4 x1a = *(const float4*)a1, x1b = *(const float4*)(a1 + 4);
    float4 x2a = *(const float4*)a2, x2b = *(const float4*)(a2 + 4);
    float4 x3a = *(const float4*)a3, x3b = *(const float4*)(a3 + 4);
#define ROW8(r, xa, xb) \
    acc[r] = fmaf(xa.x, w0, acc[r]); acc[r] = fmaf(xa.y, w1, acc[r]); \
    acc[r] = fmaf(xa.z, w2, acc[r]); acc[r] = fmaf(xa.w, w3, acc[r]); \
    acc[r] = fmaf(xb.x, w4, acc[r]); acc[r] = fmaf(xb.y, w5, acc[r]); \
    acc[r] = fmaf(xb.z, w6, acc[r]); acc[r] = fmaf(xb.w, w7, acc[r]);
    ROW8(0, x0a, x0b)
    ROW8(1, x1a, x1b)
    ROW8(2, x2a, x2b)
    ROW8(3, x3a, x3b)
#undef ROW8
}

// ---------------------------------------------------------------------------
// Fused encoder (R5 structure + k8 batching): blocks [0,64) = UAV (16 rows),
// [64,192) = task, block 192 = qb.  512 threads: j = tid&127 owns col j,
// rb = (tid>>7)*4 owns 4 of the 16 rows.
// ---------------------------------------------------------------------------
__global__ __launch_bounds__(512) void enc_fused_kernel(
    const float* __restrict__ uav_feat, const float* __restrict__ task_feat,
    const float* __restrict__ uw0, const float* __restrict__ ub0,
    const float* __restrict__ uw1, const float* __restrict__ ub1,
    const float* __restrict__ uw2, const float* __restrict__ ub2,
    const float* __restrict__ tw0, const float* __restrict__ tb0,
    const float* __restrict__ tw1, const float* __restrict__ tb1,
    const float* __restrict__ tw2, const float* __restrict__ tb2,
    const float* __restrict__ head_q, const float* __restrict__ fw1,
    const float* __restrict__ fb1)
{
    const int bx = blockIdx.x;
    const int tid = threadIdx.x;

    // ---------------- qb block ----------------
    if (bx == 192) {
        int d  = tid & 255;
        int h0 = tid >> 8;            // 0..1
        #pragma unroll
        for (int h = h0; h < H_; h += 2) {
            float acc = fb1[d];
            #pragma unroll 8
            for (int k = 0; k < E_; ++k)
                acc += head_q[h * E_ + k] * fw1[k * HID_ + d];
            g_qb[h * HID_ + d] = acc;
        }
        return;
    }

    const int is_task = (bx >= 64);
    const float* x  = is_task ? task_feat : uav_feat;
    const float* w0 = is_task ? tw0 : uw0;
    const float* b0 = is_task ? tb0 : ub0;
    const float* w1 = is_task ? tw1 : uw1;
    const float* b1 = is_task ? tb1 : ub1;
    const float* w2 = is_task ? tw2 : uw2;
    const float* b2 = is_task ? tb2 : ub2;
    float* out      = is_task ? g_kh : g_qu;
    const int fw1_off = is_task ? E_ : 0;
    const int row0 = (is_task ? (bx - 64) : bx) * 16;

    __shared__ float xs[16][IN_DIM_];
    __shared__ float bufA[16][ENC_H_];
    __shared__ float bufB[16][ENC_H_];

    // load 16x32 input tile
    if (tid < 16 * IN_DIM_)
        xs[tid >> 5][tid & 31] = x[(row0 + (tid >> 5)) * IN_DIM_ + (tid & 31)];
    __syncthreads();

    const int j  = tid & 127;
    const int rb = (tid >> 7) * 4;    // rows rb..rb+3 (warp-uniform)
    float acc[4];

    // ---- layer 0: 32 -> 128, relu ----
    {
        float bv = b0[j];
        acc[0] = acc[1] = acc[2] = acc[3] = bv;
        #pragma unroll
        for (int k = 0; k < IN_DIM_; k += 8)
            enc_step8(acc, w0 + k * ENC_H_ + j, ENC_H_,
                      &xs[rb][k], &xs[rb + 1][k], &xs[rb + 2][k], &xs[rb + 3][k]);
        #pragma unroll
        for (int r = 0; r < 4; ++r) bufA[rb + r][j] = fmaxf(acc[r], 0.f);
    }
    __syncthreads();

    // ---- layer 1: 128 -> 128, relu ----
    {
        float bv = b1[j];
        acc[0] = acc[1] = acc[2] = acc[3] = bv;
        #pragma unroll
        for (int k = 0; k < ENC_H_; k += 8)
            enc_step8(acc, w1 + k * ENC_H_ + j, ENC_H_,
                      &bufA[rb][k], &bufA[rb + 1][k], &bufA[rb + 2][k], &bufA[rb + 3][k]);
        #pragma unroll
        for (int r = 0; r < 4; ++r) bufB[rb + r][j] = fmaxf(acc[r], 0.f);
    }
    __syncthreads();

    // ---- layer 2: 128 -> 128 (no relu) ----
    {
        float bv = b2[j];
        acc[0] = acc[1] = acc[2] = acc[3] = bv;
        #pragma unroll
        for (int k = 0; k < ENC_H_; k += 8)
            enc_step8(acc, w2 + k * ENC_H_ + j, ENC_H_,
                      &bufB[rb][k], &bufB[rb + 1][k], &bufB[rb + 2][k], &bufB[rb + 3][k]);
    }
    __syncthreads();   // bufA reads done
    #pragma unroll
    for (int r = 0; r < 4; ++r) bufA[rb + r][j] = acc[r];
    __syncthreads();

    // ---- projection through fw1 slice: 128 -> 256 ----
    const float* wp = fw1 + fw1_off * HID_;
    #pragma unroll
    for (int p = 0; p < 2; ++p) {
        int col = j + p * 128;
        acc[0] = acc[1] = acc[2] = acc[3] = 0.f;
        #pragma unroll
        for (int k = 0; k < E_; k += 8)
            enc_step8(acc, wp + k * HID_ + col, HID_,
                      &bufA[rb][k], &bufA[rb + 1][k], &bufA[rb + 2][k], &bufA[rb + 3][k]);
        #pragma unroll
        for (int r = 0; r < 4; ++r)
            out[(size_t)(row0 + rb + r) * HID_ + col] = acc[r];
    }
}

// ---------------------------------------------------------------------------
// Stage E (t-split x d-half): partial[dh][z][u][t] =
//   sum_{d in half} relu(qu[b,u,d]+qb[h,d]+kh[b,t,d]) * fw2[d]
// Grid (tblk:2, dh:2, z:64) = 256 blocks, 512 threads, thread tile 4u x 2t.
// smem: qs[64][132], ks[64][132] (stride 132 -> f4-bank = tg, conflict-free),
// fw2s[128].  q/w loads warp-uniform broadcast.
// ---------------------------------------------------------------------------
#define DH 128
#define ESTR 132
#define SMEM_E_FLOATS (64 * ESTR + 64 * ESTR + DH)
#define SMEM_E_BYTES  (SMEM_E_FLOATS * 4)

__global__ __launch_bounds__(512, 2) void stageE_k(
    const float* __restrict__ fw2)
{
    extern __shared__ float smem[];
    float* qs   = smem;                        // [64][132]
    float* ks   = smem + 64 * ESTR;            // [64][132]
    float* fw2s = ks + 64 * ESTR;              // [128]

    const int tid = threadIdx.x;
    const int t0  = blockIdx.x * 64;           // 0 or 64
    const int dh  = blockIdx.y;                // 0..1
    const int z   = blockIdx.z;                // b*H + h
    const int b   = z >> 2;
    const int h   = z & 3;
    const int d0  = dh * DH;

    if (tid < DH / 4)
        ((float4*)fw2s)[tid] = ((const float4*)(fw2 + d0))[tid];

    // qs[u][dl] = qu + qb : 64 x 32 f4 = 2048 f4
    {
        const float4* qb4 = (const float4*)(g_qb + h * HID_ + d0);
        #pragma unroll
        for (int p = 0; p < 4; ++p) {
            int idx = tid + p * 512;
            int u   = idx >> 5;
            int d4  = idx & 31;
            float4 a = ((const float4*)(g_qu + (size_t)(b * U_ + u) * HID_ + d0))[d4];
            float4 qb = qb4[d4];
            a.x += qb.x; a.y += qb.y; a.z += qb.z; a.w += qb.w;
            ((float4*)(qs + u * ESTR))[d4] = a;
        }
    }
    // ks[t][dl]
    {
        #pragma unroll
        for (int p = 0; p < 4; ++p) {
            int idx = tid + p * 512;
            int t   = idx >> 5;
            int d4  = idx & 31;
            ((float4*)(ks + t * ESTR))[d4] =
                ((const float4*)(g_kh + (size_t)(b * T_ + t0 + t) * HID_ + d0))[d4];
        }
    }
    __syncthreads();

    const int tg = tid & 31;       // t = t0 + tg + 32*jj (jj 0..1)
    const int ug = tid >> 5;       // u = ug*4 + i (warp-uniform)

    ull acc[4][2];
    #pragma unroll
    for (int i = 0; i < 4; ++i) { acc[i][0] = 0ULL; acc[i][1] = 0ULL; }

    const float* qbase = qs + (ug * 4) * ESTR;
    const float* kbase = ks + tg * ESTR;

    #pragma unroll 4
    for (int d4 = 0; d4 < DH / 4; ++d4) {
        ulonglong2 wv = *(const ulonglong2*)(fw2s + d4 * 4);
        ulonglong2 qv[4], kv[2];
        #pragma unroll
        for (int i = 0; i < 4; ++i)
            qv[i] = *(const ulonglong2*)(qbase + i * ESTR + d4 * 4);
        #pragma unroll
        for (int jj = 0; jj < 2; ++jj)
            kv[jj] = *(const ulonglong2*)(kbase + jj * 32 * ESTR + d4 * 4);

        #pragma unroll
        for (int i = 0; i < 4; ++i) {
            #pragma unroll
            for (int jj = 0; jj < 2; ++jj) {
                fma2(acc[i][jj], relu2(add2(qv[i].x, kv[jj].x)), wv.x);
                fma2(acc[i][jj], relu2(add2(qv[i].y, kv[jj].y)), wv.y);
            }
        }
    }

    float* part = g_part[dh] + (size_t)z * U_ * T_;
    #pragma unroll
    for (int i = 0; i < 4; ++i) {
        float* row = part + (ug * 4 + i) * T_ + t0 + tg;
        row[0]  = hsum2(acc[i][0]);
        row[32] = hsum2(acc[i][1]);
    }
}

// ---------------------------------------------------------------------------
// Combine: out = part0 + part1 + fb2 (1 float4 per thread, 512 blocks)
// ---------------------------------------------------------------------------
__global__ __launch_bounds__(256) void combine_kernel(
    float* __restrict__ out, const float* __restrict__ fb2)
{
    const float bias = fb2[0];
    int i = blockIdx.x * 256 + threadIdx.x;      // float4 index, 131072 total
    float4 a = ((const float4*)g_part[0])[i];
    float4 b = ((const float4*)g_part[1])[i];
    float4 r;
    r.x = a.x + b.x + bias;
    r.y = a.y + b.y + bias;
    r.z = a.z + b.z + bias;
    r.w = a.w + b.w + bias;
    ((float4*)out)[i] = r;
}

// ---------------------------------------------------------------------------
extern "C" void kernel_launch(void* const* d_in, const int* in_sizes, int n_in,
                              void* d_out, int out_size)
{
    const float* uav_feat = (const float*)d_in[0];
    const float* task_feat = (const float*)d_in[1];
    const float* uw0 = (const float*)d_in[2];
    const float* ub0 = (const float*)d_in[3];
    const float* uw1 = (const float*)d_in[4];
    const float* ub1 = (const float*)d_in[5];
    const float* uw2 = (const float*)d_in[6];
    const float* ub2 = (const float*)d_in[7];
    const float* tw0 = (const float*)d_in[8];
    const float* tb0 = (const float*)d_in[9];
    const float* tw1 = (const float*)d_in[10];
    const float* tb1 = (const float*)d_in[11];
    const float* tw2 = (const float*)d_in[12];
    const float* tb2 = (const float*)d_in[13];
    const float* head_q = (const float*)d_in[14];
    const float* fw1 = (const float*)d_in[15];
    const float* fb1 = (const float*)d_in[16];
    const float* fw2 = (const float*)d_in[17];
    const float* fb2 = (const float*)d_in[18];
    float* out = (float*)d_out;

    cudaFuncSetAttribute(stageE_k,
                         cudaFuncAttributeMaxDynamicSharedMemorySize,
                         SMEM_E_BYTES);

    // Encoders + qb (193 blocks x 512 threads, 16 rows/block)
    enc_fused_kernel<<<193, 512>>>(uav_feat, task_feat,
                                   uw0, ub0, uw1, ub1, uw2, ub2,
                                   tw0, tb0, tw1, tb1, tw2, tb2,
                                   head_q, fw1, fb1);

    // Stage E over (t:2, d-half:2, z:64)
    dim3 grid(2, 2, B_ * H_);
    stageE_k<<<grid, 512, SMEM_E_BYTES>>>(fw2);

    // Combine partials + bias
    combine_kernel<<<512, 256>>>(out, fb2);
}